// round 3
// baseline (speedup 1.0000x reference)
#include <cuda_runtime.h>

#define SS 512
#define BB 64
#define HH 8
#define KK 12
#define PP 9
#define TT 4096
#define THRESH 4

// parity per (h, s, b) — fully overwritten every launch, then reduced.
__device__ unsigned char g_par[HH * SS * BB];

__global__ void __launch_bounds__(256) softram_main_kernel(
    const int* __restrict__ tokens,   // (S, B)
    const int* __restrict__ conn,     // (H, B, K)
    const float* __restrict__ ram)    // (H, B, T)
{
    const int hb  = blockIdx.x;          // 0..H*B-1
    const int h   = hb >> 6;             // / B
    const int b   = hb & (BB - 1);
    const int tid = threadIdx.x;

    __shared__ int sc[KK];
    __shared__ unsigned short sAq[SS];
    __shared__ unsigned short sAk[SS];
    __shared__ unsigned short sAr[SS];
    __shared__ unsigned int   sbits[TT / 32];   // 128 words = 512 B

    if (tid < KK) sc[tid] = conn[(h * BB + b) * KK + tid];
    __syncthreads();

    // ---- build address components for all 512 positions ----
    for (int s = tid; s < SS; s += 256) {
        int aq = 0, ak = 0, ar = 0;
        #pragma unroll
        for (int k = 0; k < KK; ++k) {
            const int c = sc[k];
            if (c < BB) {
                aq += (tokens[s * BB + c] & 1) << k;
            } else if (c < 2 * BB) {
                ak += (tokens[s * BB + (c - BB)] & 1) << k;
            } else {
                ar += ((s >> (c - 2 * BB)) & 1) << k;
            }
        }
        sAq[s] = (unsigned short)aq;
        sAk[s] = (unsigned short)ak;
        sAr[s] = (unsigned short)ar;
    }

    // ---- bit-pack this (h,b)'s RAM: 4096 floats (0/1) -> 128 words ----
    {
        const int base = (h * BB + b) * TT;
        for (int t = tid; t < TT; t += 256) {
            const unsigned bit = (ram[base + t] > 0.5f) ? 1u : 0u;
            const unsigned word = __ballot_sync(0xffffffffu, bit);
            if ((tid & 31) == 0) sbits[t >> 5] = word;
        }
    }
    __syncthreads();

    // ---- main triangular XOR-gather: rows tid and 511-tid (balanced: 513 iters/thread) ----
    #pragma unroll
    for (int r = 0; r < 2; ++r) {
        const int i  = (r == 0) ? tid : (SS - 1 - tid);
        const int aq = sAq[i];

        unsigned acc0 = 0, acc1 = 0, acc2 = 0, acc3 = 0;
        int j = 0;
        const int n = i + 1;               // j in [0, i]
        for (; j + 3 < n; j += 4) {
            const int t0 = aq + sAk[j + 0] + sAr[i - j - 0];
            const int t1 = aq + sAk[j + 1] + sAr[i - j - 1];
            const int t2 = aq + sAk[j + 2] + sAr[i - j - 2];
            const int t3 = aq + sAk[j + 3] + sAr[i - j - 3];
            acc0 ^= sbits[t0 >> 5] >> (t0 & 31);
            acc1 ^= sbits[t1 >> 5] >> (t1 & 31);
            acc2 ^= sbits[t2 >> 5] >> (t2 & 31);
            acc3 ^= sbits[t3 >> 5] >> (t3 & 31);
        }
        for (; j < n; ++j) {
            const int t0 = aq + sAk[j] + sAr[i - j];
            acc0 ^= sbits[t0 >> 5] >> (t0 & 31);
        }
        const unsigned parity = (acc0 ^ acc1 ^ acc2 ^ acc3) & 1u;
        g_par[(h * SS + i) * BB + b] = (unsigned char)parity;
    }
}

__global__ void __launch_bounds__(256) softram_reduce_kernel(float* __restrict__ out)
{
    const int idx = blockIdx.x * 256 + threadIdx.x;   // idx = s*B + b
    if (idx >= SS * BB) return;
    int sum = 0;
    #pragma unroll
    for (int h = 0; h < HH; ++h) sum += g_par[h * SS * BB + idx];
    out[idx] = (sum > THRESH) ? 1.0f : 0.0f;
}

extern "C" void kernel_launch(void* const* d_in, const int* in_sizes, int n_in,
                              void* d_out, int out_size)
{
    const int*   tokens = (const int*)d_in[0];
    const int*   conn   = (const int*)d_in[1];
    const float* ram    = (const float*)d_in[2];
    float*       out    = (float*)d_out;

    softram_main_kernel<<<HH * BB, 256>>>(tokens, conn, ram);
    softram_reduce_kernel<<<(SS * BB + 255) / 256, 256>>>(out);
}